// round 15
// baseline (speedup 1.0000x reference)
#include <cuda_runtime.h>
#include <cuda_bf16.h>

// VectorQuantizer forward, single fused PERSISTENT kernel:
//   q    = codebook[categories]   (row gather, 512x768 codebook -> L2 resident)
//   out  = q
//   loss = 1.25 * mean((q - inputs)^2)
//
// Persistent grid: 148 SMs x 8 blocks = 1184 blocks = exactly one residency
// wave; each block grid-strides over 4096 tiles of 16 rows. Removes 2912
// block launch/drain transitions and cuts epilogues/atomics 4096 -> 1184.
//
// Loss reduction: one packed 64-bit integer atomicAdd per block.
//   bits [0:50)  : fixed-point (2^20) partial sum (max ~4e14 < 2^50)
//   bits [50:64) : block-arrival count (14 bits >= 1184 blocks)
// Integer adds are associative -> bit-deterministic; the atomicAdd return
// value lets the last block detect completion AND recover the full sum.
//
// Index distribution: warp-local (lane l<16 loads the tile's cat entries,
// rows recovered via __shfl_sync). No smem/barrier on the index path.
//
// Measured config (GB300, R3-R14): TPB=256 @ 8 blk/SM = 64/64 warps, regs 32,
// unroll 4, plain LDG/STG (streaming hints harmful). DRAM ceiling ~74-75%.
//
// inputs:     [65536, 768] f32
// categories: [65536]      int32
// codebook:   [512, 768]   f32
// out:        65536*768 f32 quantized_st, then 1 f32 loss (if out_size permits)

#define VQ_BS    65536
#define VQ_D4    192                  // float4s per row
#define VQ_ROWS  16                   // rows per tile
#define VQ_TPB   256                  // threads per block
#define VQ_F4PT  (VQ_ROWS * VQ_D4)    // 3072 float4s per tile
#define VQ_ITERS (VQ_F4PT / VQ_TPB)   // 12 per thread per tile
#define VQ_NTILE (VQ_BS / VQ_ROWS)    // 4096 tiles
#define VQ_NBLK  (148 * 8)            // 1184 persistent blocks (one wave)

#define VQ_CNT_SHIFT 50
#define VQ_FX_SCALE  1048576.0        // 2^20

__device__ unsigned long long g_vq_acc = 0ULL;   // reset by last block -> replay-idempotent

__global__ __launch_bounds__(VQ_TPB, 8) void vq_kernel(
    const float4* __restrict__ in,
    const int* __restrict__ cat,
    const float4* __restrict__ cb,
    float4* __restrict__ out,
    float* __restrict__ loss_out,
    int write_loss)
{
    const int t    = threadIdx.x;                    // 0..255
    const int lane = t & 31;

    float s = 0.0f;

    for (int tile = blockIdx.x; tile < VQ_NTILE; tile += VQ_NBLK) {
        const size_t tile_f4 = (size_t)tile * VQ_F4PT;

        // Warp-local index copy for this tile: lane l < VQ_ROWS holds cat[..+l].
        int my_c = 0;
        if (lane < VQ_ROWS)
            my_c = __ldg(&cat[tile * VQ_ROWS + lane]) & 511;   // mask: no-op on valid data

        #pragma unroll 4
        for (int k = 0; k < VQ_ITERS; k++) {
            const int idx = t + k * VQ_TPB;          // 0..3071 within tile
            const int row = idx / VQ_D4;             // const-div -> mul/shift
            const int col = idx - row * VQ_D4;
            const int c   = __shfl_sync(0xffffffffu, my_c, row);
            const size_t gib = tile_f4 + idx;        // flat, fully coalesced
            float4 a = in[gib];
            float4 q = cb[(size_t)c * VQ_D4 + col];
            out[gib] = q;
            float dx = q.x - a.x;
            float dy = q.y - a.y;
            float dz = q.z - a.z;
            float dw = q.w - a.w;
            s += dx*dx + dy*dy + dz*dz + dw*dw;
        }
    }

    // block reduction: 8 warps of 32
    #pragma unroll
    for (int o = 16; o > 0; o >>= 1)
        s += __shfl_down_sync(0xffffffffu, s, o);

    __shared__ float ws[8];
    if ((t & 31) == 0) ws[t >> 5] = s;
    __syncthreads();

    if (t == 0) {
        float tot = ws[0] + ws[1] + ws[2] + ws[3] + ws[4] + ws[5] + ws[6] + ws[7];
        // fixed-point: ~3.3e5 per block -> ~3.5e11 scaled; total ~4e14 < 2^50
        unsigned long long fx = (unsigned long long)((double)tot * VQ_FX_SCALE);
        unsigned long long packed = (1ULL << VQ_CNT_SHIFT) + fx;
        unsigned long long old = atomicAdd(&g_vq_acc, packed);

        if ((old >> VQ_CNT_SHIFT) == (unsigned long long)(VQ_NBLK - 1)) {
            unsigned long long full = (old + packed) & ((1ULL << VQ_CNT_SHIFT) - 1ULL);
            if (write_loss) {
                const double inv_n = 1.0 / ((double)VQ_BS * 768.0);
                double mse = ((double)full / VQ_FX_SCALE) * inv_n;
                // loss = (CODEBOOK_COST + COMMITMENT_COST) * mse = 1.25 * mse
                loss_out[(size_t)VQ_BS * 768] = (float)(1.25 * mse);
            }
            g_vq_acc = 0ULL;   // reset for next graph replay (no other block alive)
        }
    }
}

extern "C" void kernel_launch(void* const* d_in, const int* in_sizes, int n_in,
                              void* d_out, int out_size)
{
    const float4* in  = (const float4*)d_in[0];
    const int*    cat = (const int*)d_in[1];
    const float4* cb  = (const float4*)d_in[2];
    float*        out = (float*)d_out;

    const int write_loss = (out_size > VQ_BS * 768) ? 1 : 0;
    vq_kernel<<<VQ_NBLK, VQ_TPB>>>(in, cat, cb, (float4*)out, out, write_loss);
}

// round 16
// speedup vs baseline: 1.1044x; 1.1044x over previous
#include <cuda_runtime.h>
#include <cuda_bf16.h>

// VectorQuantizer forward, single fused kernel — FINAL (best-measured total, R12).
//   q    = codebook[categories]   (row gather, 512x768 codebook -> L2 resident)
//   out  = q
//   loss = 1.25 * mean((q - inputs)^2)
//
// Loss reduction: one packed 64-bit integer atomicAdd per block.
//   bits [0:50)  : fixed-point (2^20) partial sum (max ~1.05e14 < 2^50)
//   bits [50:64) : block-arrival count (14 bits, max 16383 >= 8192 blocks)
// Integer adds are associative -> bit-deterministic; the atomicAdd return
// value lets the last block detect completion AND recover the full sum
// (no fence, no second pass, no second kernel).
//
// Search closed (GB300, R3-R15, all measured):
//  - TPB=256 @ 8 blk/SM = 64/64 warps, regs 32 (RF exactly full). Best.
//  - ROWS=8 (8192 blocks): best recorded total 65.6us; many small blocks
//    self-balance. Persistent 1184-block grid: straggler tail, total 72.4. NO.
//  - __ldcs/__stcs harmful (~2.7us). __threadfence tail harmful (~3-5us).
//  - unroll 3 here (6 iters); unroll 8 blew regs to 40 earlier.
//  - DRAM pinned 73-75% (5.83-5.94 TB/s) across every shape = practical HBM3e
//    ceiling for 1:1 interleaved read:write; 384MB payload irreducible.
//
// inputs:     [65536, 768] f32
// categories: [65536]      int32
// codebook:   [512, 768]   f32
// out:        65536*768 f32 quantized_st, then 1 f32 loss (if out_size permits)

#define VQ_BS    65536
#define VQ_D4    192                  // float4s per row
#define VQ_ROWS  8                    // rows per block
#define VQ_TPB   256                  // threads per block
#define VQ_F4PB  (VQ_ROWS * VQ_D4)    // 1536 float4s per block
#define VQ_ITERS (VQ_F4PB / VQ_TPB)   // 6 per thread
#define VQ_NBLK  (VQ_BS / VQ_ROWS)    // 8192 blocks

#define VQ_CNT_SHIFT 50
#define VQ_FX_SCALE  1048576.0        // 2^20

__device__ unsigned long long g_vq_acc = 0ULL;   // reset by last block -> replay-idempotent

__global__ __launch_bounds__(VQ_TPB, 8) void vq_kernel(
    const float4* __restrict__ in,
    const int* __restrict__ cat,
    const float4* __restrict__ cb,
    float4* __restrict__ out,
    float* __restrict__ loss_out,
    int write_loss)
{
    const int t = threadIdx.x;                       // 0..255
    const int row_base = blockIdx.x * VQ_ROWS;
    const size_t blk_f4 = (size_t)blockIdx.x * VQ_F4PB;

    // Hoist index gather once per block.
    __shared__ int scat[VQ_ROWS];
    if (t < VQ_ROWS) scat[t] = cat[row_base + t] & 511;   // mask: no-op on valid data
    __syncthreads();

    float s = 0.0f;

    #pragma unroll 3
    for (int k = 0; k < VQ_ITERS; k++) {
        const int idx = t + k * VQ_TPB;              // 0..1535 within block tile
        const int row = idx / VQ_D4;                 // const-div -> mul/shift
        const int col = idx - row * VQ_D4;
        const size_t gib = blk_f4 + idx;             // flat, fully coalesced
        float4 a = in[gib];
        float4 q = cb[(size_t)scat[row] * VQ_D4 + col];
        out[gib] = q;
        float dx = q.x - a.x;
        float dy = q.y - a.y;
        float dz = q.z - a.z;
        float dw = q.w - a.w;
        s += dx*dx + dy*dy + dz*dz + dw*dw;
    }

    // block reduction: 8 warps of 32
    #pragma unroll
    for (int o = 16; o > 0; o >>= 1)
        s += __shfl_down_sync(0xffffffffu, s, o);

    __shared__ float ws[8];
    if ((t & 31) == 0) ws[t >> 5] = s;
    __syncthreads();

    if (t == 0) {
        float tot = ws[0] + ws[1] + ws[2] + ws[3] + ws[4] + ws[5] + ws[6] + ws[7];
        // fixed-point: ~1.2e4 per block -> ~1.3e10 scaled; total ~1.05e14 < 2^50
        unsigned long long fx = (unsigned long long)((double)tot * VQ_FX_SCALE);
        unsigned long long packed = (1ULL << VQ_CNT_SHIFT) + fx;
        unsigned long long old = atomicAdd(&g_vq_acc, packed);

        if ((old >> VQ_CNT_SHIFT) == (unsigned long long)(VQ_NBLK - 1)) {
            unsigned long long full = (old + packed) & ((1ULL << VQ_CNT_SHIFT) - 1ULL);
            if (write_loss) {
                const double inv_n = 1.0 / ((double)VQ_BS * 768.0);
                double mse = ((double)full / VQ_FX_SCALE) * inv_n;
                // loss = (CODEBOOK_COST + COMMITMENT_COST) * mse = 1.25 * mse
                loss_out[(size_t)VQ_BS * 768] = (float)(1.25 * mse);
            }
            g_vq_acc = 0ULL;   // reset for next graph replay (no other block alive)
        }
    }
}

extern "C" void kernel_launch(void* const* d_in, const int* in_sizes, int n_in,
                              void* d_out, int out_size)
{
    const float4* in  = (const float4*)d_in[0];
    const int*    cat = (const int*)d_in[1];
    const float4* cb  = (const float4*)d_in[2];
    float*        out = (float*)d_out;

    const int write_loss = (out_size > VQ_BS * 768) ? 1 : 0;
    vq_kernel<<<VQ_NBLK, VQ_TPB>>>(in, cat, cb, (float4*)out, out, write_loss);
}